// round 15
// baseline (speedup 1.0000x reference)
#include <cuda_runtime.h>
#include <cuda_fp16.h>
#include <math.h>
#include <stdint.h>

#define HN 16
#define DHD 64
#define DD 1024
#define BB 2
#define SS 2048
#define MROWS (BB * SS)   // 4096

// ------------------------- device scratch (no allocs) -----------------------
__device__ __align__(16) __half g_xh[MROWS * DD];            // X fp16 (single)
__device__ __align__(16) __half g_wht[4][DD * DD];           // W^T hi [N][K]
__device__ __align__(16) __half g_wlt[4][DD * DD];           // W^T lo [N][K]
__device__ __align__(16) __half g_qh[BB * HN * SS * DHD];    // Q fp16, scaled 0.125*log2e
__device__ __align__(16) __half g_kh[BB * HN * SS * DHD];    // K hi
__device__ __align__(16) __half g_kl[BB * HN * SS * DHD];    // K lo
__device__ __align__(16) __half g_vth[BB * HN * SS * DHD];   // V^T hi [b,h,dh,s]
__device__ __align__(16) __half g_vtl[BB * HN * SS * DHD];   // V^T lo
__device__ __align__(16) __half g_ch[MROWS * DD];            // ctx fp16 (single)

#define QSCALE (0.125f * 1.44269504088896340736f)

// ------------------------------ ptx helpers --------------------------------
__device__ __forceinline__ uint32_t smem_u32(const void* p) {
    return (uint32_t)__cvta_generic_to_shared(p);
}
__device__ __forceinline__ void cpa16(uint32_t d, const void* s) {
    asm volatile("cp.async.cg.shared.global [%0], [%1], 16;" :: "r"(d), "l"(s));
}
__device__ __forceinline__ void cpa_commit() {
    asm volatile("cp.async.commit_group;" ::: "memory");
}
__device__ __forceinline__ void ldsm_x4(uint32_t& d0, uint32_t& d1, uint32_t& d2,
                                        uint32_t& d3, uint32_t addr) {
    asm volatile("ldmatrix.sync.aligned.m8n8.x4.shared.b16 {%0,%1,%2,%3}, [%4];"
                 : "=r"(d0), "=r"(d1), "=r"(d2), "=r"(d3) : "r"(addr));
}
__device__ __forceinline__ void mma_f16(float* c, const uint32_t* a,
                                        uint32_t b0, uint32_t b1) {
    asm volatile(
        "mma.sync.aligned.m16n8k16.row.col.f32.f16.f16.f32 "
        "{%0,%1,%2,%3}, {%4,%5,%6,%7}, {%8,%9}, {%0,%1,%2,%3};"
        : "+f"(c[0]), "+f"(c[1]), "+f"(c[2]), "+f"(c[3])
        : "r"(a[0]), "r"(a[1]), "r"(a[2]), "r"(a[3]), "r"(b0), "r"(b1));
}
__device__ __forceinline__ uint32_t h2pack(float x, float y) {
    __half2 t = __floats2half2_rn(x, y);
    return *reinterpret_cast<uint32_t*>(&t);
}
__device__ __forceinline__ void split2h(float x, float y, uint32_t& h, uint32_t& l) {
    __half2 hh = __floats2half2_rn(x, y);
    __half2 ll = __floats2half2_rn(x - __low2float(hh), y - __high2float(hh));
    h = *reinterpret_cast<uint32_t*>(&hh);
    l = *reinterpret_cast<uint32_t*>(&ll);
}
__device__ __forceinline__ float fexp2(float x) {
    float y;
    asm("ex2.approx.ftz.f32 %0, %1;" : "=f"(y) : "f"(x));
    return y;
}

// ---------------------------- conversion kernels ---------------------------
__global__ __launch_bounds__(256)
void convert_x_kernel(const float* __restrict__ X, __half* __restrict__ Xh) {
    size_t i = (size_t)blockIdx.x * blockDim.x + threadIdx.x;
    float4 v = reinterpret_cast<const float4*>(X)[i];
    uint2 o;
    o.x = h2pack(v.x, v.y);
    o.y = h2pack(v.z, v.w);
    reinterpret_cast<uint2*>(Xh)[i] = o;
}

__global__ __launch_bounds__(256)
void convert_wT_kernel(const float* __restrict__ W0, const float* __restrict__ W1,
                       const float* __restrict__ W2, const float* __restrict__ W3) {
    __shared__ float t[32][33];
    const int w = blockIdx.z;
    const float* W = (w == 0) ? W0 : (w == 1) ? W1 : (w == 2) ? W2 : W3;
    __half* WhT = g_wht[w];
    __half* WlT = g_wlt[w];
    int n0 = blockIdx.x * 32, k0 = blockIdx.y * 32;
    int tx = threadIdx.x & 31;
    int ty = threadIdx.x >> 5;
#pragma unroll
    for (int j = 0; j < 4; j++)
        t[ty + 8 * j][tx] = W[(size_t)(k0 + ty + 8 * j) * DD + n0 + tx];
    __syncthreads();
#pragma unroll
    for (int j = 0; j < 4; j++) {
        float v = t[tx][ty + 8 * j];
        __half h = __float2half_rn(v);
        size_t o = (size_t)(n0 + ty + 8 * j) * DD + k0 + tx;
        WhT[o] = h;
        WlT[o] = __float2half_rn(v - __half2float(h));
    }
}

// ------------------------- mma.sync fp16 2-pass GEMM ------------------------
#define BM 128
#define BN 128
#define BK 32
#define NCH (DD / BK)       // 32
#define MAT_B (BM * BK * 2) // 8192
#define STG_B (3 * MAT_B)   // 24576 : A, Bh, Bl
#define NSTG 4
#define GEMM_SMEM (NSTG * STG_B)  // 98304

__device__ __forceinline__ uint32_t soff(int r, int c) {
    return (uint32_t)(r * 64 + ((c ^ ((r >> 1) & 3)) << 4));
}

__device__ __forceinline__ void load_stage(uint32_t sb,
                                           const __half* A,
                                           const __half* Bh, const __half* Bl,
                                           int m0, int n0, int chunk, int tid) {
    const int kb = chunk * BK;
#pragma unroll
    for (int t = 0; t < 6; t++) {
        int idx = t * 256 + tid;        // 0..1535
        int mat = idx >> 9;             // 0..2
        int i = idx & 511;
        int r = i >> 2;
        int c = i & 3;
        uint32_t d = sb + mat * MAT_B + soff(r, c);
        const __half* src;
        if (mat == 0)      src = A  + (size_t)(m0 + r) * DD + kb + c * 8;
        else if (mat == 1) src = Bh + (size_t)(n0 + r) * DD + kb + c * 8;
        else               src = Bl + (size_t)(n0 + r) * DD + kb + c * 8;
        cpa16(d, (const void*)src);
    }
    cpa_commit();
}

// QKV=1: grid.z = proj (0=Q scaled single, 1=K split, 2=V split transposed)
// QKV=0: fp32 row-major out + bias0.
template <int QKV>
__global__ __launch_bounds__(256, 2)
void gemm_tc_kernel(const __half* __restrict__ A,
                    const float* __restrict__ b0, const float* __restrict__ b1,
                    const float* __restrict__ b2, float* __restrict__ Y) {
    extern __shared__ char dsm[];
    const int tid = threadIdx.x;
    const int lane = tid & 31;
    const int wid = tid >> 5;
    const int mwarp = wid & 3;
    const int nwarp = wid >> 2;
    const int n0 = blockIdx.x * BN;
    const int m0 = blockIdx.y * BM;
    const int proj = QKV ? blockIdx.z : 3;

    const __half* Bh = g_wht[proj];
    const __half* Bl = g_wlt[proj];
    const float* bias = QKV ? ((proj == 0) ? b0 : (proj == 1) ? b1 : b2) : b0;

    const uint32_t sbase = smem_u32(dsm);
    const int lr = lane & 7;
    const int lg = lane >> 3;

    float acc[2][8][4];
#pragma unroll
    for (int mt = 0; mt < 2; mt++)
#pragma unroll
        for (int nt = 0; nt < 8; nt++)
#pragma unroll
            for (int r = 0; r < 4; r++) acc[mt][nt][r] = 0.0f;

    load_stage(sbase, A, Bh, Bl, m0, n0, 0, tid);
    load_stage(sbase + STG_B, A, Bh, Bl, m0, n0, 1, tid);
    load_stage(sbase + 2 * STG_B, A, Bh, Bl, m0, n0, 2, tid);

    for (int c = 0; c < NCH; c++) {
        const int rem = NCH - 1 - c;
        if (rem >= 2)      asm volatile("cp.async.wait_group 2;" ::: "memory");
        else if (rem == 1) asm volatile("cp.async.wait_group 1;" ::: "memory");
        else               asm volatile("cp.async.wait_group 0;" ::: "memory");
        __syncthreads();
        if (c + 3 < NCH)
            load_stage(sbase + (uint32_t)((c + 3) & 3) * STG_B, A, Bh, Bl, m0, n0, c + 3, tid);

        const uint32_t sb = sbase + (uint32_t)(c & 3) * STG_B;
        const uint32_t sA  = sb;
        const uint32_t sBh = sb + MAT_B;
        const uint32_t sBl = sb + 2 * MAT_B;

#pragma unroll
        for (int ks = 0; ks < 2; ks++) {
            const int c0 = ks * 2;
            uint32_t av[2][4];
#pragma unroll
            for (int mt = 0; mt < 2; mt++) {
                int row = mwarp * 32 + mt * 16 + lr + (lg & 1) * 8;
                int ch = c0 + (lg >> 1);
                ldsm_x4(av[mt][0], av[mt][1], av[mt][2], av[mt][3], sA + soff(row, ch));
            }
#pragma unroll
            for (int np = 0; np < 4; np++) {
                int brow = nwarp * 64 + np * 16 + lr + (lg >> 1) * 8;
                int bch = c0 + (lg & 1);
                uint32_t boff = soff(brow, bch);
                uint32_t bh0, bh1, bh2, bh3, bl0, bl1, bl2, bl3;
                ldsm_x4(bh0, bh1, bh2, bh3, sBh + boff);
                ldsm_x4(bl0, bl1, bl2, bl3, sBl + boff);
#pragma unroll
                for (int mt = 0; mt < 2; mt++) {
                    mma_f16(acc[mt][2 * np + 0], av[mt], bh0, bh1);
                    mma_f16(acc[mt][2 * np + 1], av[mt], bh2, bh3);
                    mma_f16(acc[mt][2 * np + 0], av[mt], bl0, bl1);
                    mma_f16(acc[mt][2 * np + 1], av[mt], bl2, bl3);
                }
            }
        }
    }

    // epilogue
#pragma unroll
    for (int mt = 0; mt < 2; mt++) {
#pragma unroll
        for (int half = 0; half < 2; half++) {
            int gm = m0 + mwarp * 32 + mt * 16 + (lane >> 2) + half * 8;
            int bidx = gm >> 11;
            int sidx = gm & (SS - 1);
#pragma unroll
            for (int nt = 0; nt < 8; nt++) {
                int ncol = n0 + nwarp * 64 + nt * 8 + 2 * (lane & 3);
                float2 bv = *reinterpret_cast<const float2*>(&bias[ncol]);
                float ox = acc[mt][nt][2 * half + 0] + bv.x;
                float oy = acc[mt][nt][2 * half + 1] + bv.y;
                if (!QKV) {
                    float2 o = {ox, oy};
                    *reinterpret_cast<float2*>(&Y[(size_t)gm * DD + ncol]) = o;
                } else {
                    int hh = ncol >> 6;
                    int dh = ncol & (DHD - 1);
                    if (proj == 0) {
                        size_t base = (((size_t)bidx * HN + hh) * SS + sidx) * DHD + dh;
                        *reinterpret_cast<uint32_t*>(&g_qh[base]) =
                            h2pack(ox * QSCALE, oy * QSCALE);
                    } else if (proj == 1) {
                        uint32_t hq, lq;
                        split2h(ox, oy, hq, lq);
                        size_t base = (((size_t)bidx * HN + hh) * SS + sidx) * DHD + dh;
                        *reinterpret_cast<uint32_t*>(&g_kh[base]) = hq;
                        *reinterpret_cast<uint32_t*>(&g_kl[base]) = lq;
                    } else {
                        uint32_t hq, lq;
                        split2h(ox, oy, hq, lq);
                        size_t base = (((size_t)bidx * HN + hh) * DHD + dh) * SS + sidx;
                        __half2 hv = *reinterpret_cast<__half2*>(&hq);
                        __half2 lv = *reinterpret_cast<__half2*>(&lq);
                        g_vth[base] = __low2half(hv); g_vth[base + SS] = __high2half(hv);
                        g_vtl[base] = __low2half(lv); g_vtl[base + SS] = __high2half(lv);
                    }
                }
            }
        }
    }
}

// ---------------------- tensor-core flash attention (fp16) ------------------
// 4 warps x 32 q-rows each (2 m16 tiles): K/V ldsm amortized over 2x MMA.
// 3-stage KV ring, one barrier/tile, base-2 softmax, per-warp tile skip.
#define AQ_B 16384                 // Q: 128 rows x 128B
#define AT_B 8192                  // K/V^T: 64 rows x 128B
#define ASTG_B (4 * AT_B)          // Kh, Kl, VTh, VTl = 32768
#define ANSTG 3
#define ATT_SMEM (AQ_B + ANSTG * ASTG_B)  // 114688
#define ATHR 128

__device__ __forceinline__ uint32_t aoff(int r, int c) {
    return (uint32_t)(r * 128 + ((c ^ (r & 7)) << 4));
}

__device__ __forceinline__ void att_load_kv(uint32_t sb, size_t hb, int s0, int tid) {
#pragma unroll
    for (int t = 0; t < 16; t++) {
        int slot = t * ATHR + tid;      // 0..2047
        int mat = slot >> 9;
        int i = slot & 511;
        int r = i >> 3;
        int c = i & 7;
        uint32_t d = sb + mat * AT_B + aoff(r, c);
        const __half* src;
        if (mat == 0)      src = g_kh + hb + (size_t)(s0 + r) * DHD + c * 8;
        else if (mat == 1) src = g_kl + hb + (size_t)(s0 + r) * DHD + c * 8;
        else if (mat == 2) src = g_vth + hb + (size_t)r * SS + s0 + c * 8;
        else               src = g_vtl + hb + (size_t)r * SS + s0 + c * 8;
        cpa16(d, (const void*)src);
    }
}

__global__ __launch_bounds__(ATHR, 2)
void attn_kernel() {
    extern __shared__ char asm_[];
    const uint32_t sbase = smem_u32(asm_);
    const uint32_t kvbase = sbase + AQ_B;
    const int tid = threadIdx.x;
    const int lane = tid & 31;
    const int wid = tid >> 5;        // 0..3
    const int lr = lane & 7;
    const int lg = lane >> 3;
    const int g = lane >> 2;
    const int t4 = lane & 3;

    const int Qi = 15 - blockIdx.x;
    const int h = blockIdx.y;
    const int b = blockIdx.z;
    const int q0 = Qi * 128;
    const size_t hb = ((size_t)b * HN + h) * SS * DHD;
    const int ntiles = 2 * Qi + 2;

    {   // prologue: Q + stage0 (group 0); stage1 (group 1)
#pragma unroll
        for (int t = 0; t < 8; t++) {
            int idx = t * ATHR + tid;    // 0..1023
            int r = idx >> 3;
            int c = idx & 7;
            cpa16(sbase + aoff(r, c), (const void*)(g_qh + hb + (size_t)(q0 + r) * DHD + c * 8));
        }
        att_load_kv(kvbase, hb, 0, tid);
        cpa_commit();
        att_load_kv(kvbase + ASTG_B, hb, 64, tid);
        cpa_commit();
    }

    float S[2][8][4];
    float ctx[2][8][4];
    uint32_t qf[2][4][4];
    float mrow[2][2] = {{-INFINITY, -INFINITY}, {-INFINITY, -INFINITY}};
    float lrow[2][2] = {{0.0f, 0.0f}, {0.0f, 0.0f}};
#pragma unroll
    for (int mt = 0; mt < 2; mt++)
#pragma unroll
        for (int t = 0; t < 8; t++)
#pragma unroll
            for (int r = 0; r < 4; r++) ctx[mt][t][r] = 0.0f;

    const int wrow0 = q0 + wid * 32;             // warp's first row
    const int myrow0 = wrow0 + g;                // mt=0 base row for this thread
    int slot = 0;

    for (int kt = 0; kt < ntiles; kt++) {
        const uint32_t stb = kvbase + (uint32_t)slot * ASTG_B;
        const int rem = ntiles - 1 - kt;
        if (rem >= 1) asm volatile("cp.async.wait_group 1;" ::: "memory");
        else          asm volatile("cp.async.wait_group 0;" ::: "memory");
        __syncthreads();

        if (kt == 0) {
#pragma unroll
            for (int mt = 0; mt < 2; mt++)
#pragma unroll
                for (int k16 = 0; k16 < 4; k16++) {
                    uint32_t qo = aoff(wid * 32 + mt * 16 + lr + (lg & 1) * 8,
                                       2 * k16 + (lg >> 1));
                    ldsm_x4(qf[mt][k16][0], qf[mt][k16][1], qf[mt][k16][2],
                            qf[mt][k16][3], sbase + qo);
                }
        }
        // prefetch tile kt+2 BEFORE compute
        if (kt + 2 < ntiles) {
            int ns = slot + 2; if (ns >= ANSTG) ns -= ANSTG;
            att_load_kv(kvbase + (uint32_t)ns * ASTG_B, hb, (kt + 2) * 64, tid);
            cpa_commit();
        }

        const int kb = kt * 64;
        if (kb <= wrow0 + 31) {   // warp has at least one unmasked row
#pragma unroll
            for (int mt = 0; mt < 2; mt++)
#pragma unroll
                for (int t = 0; t < 8; t++)
#pragma unroll
                    for (int r = 0; r < 4; r++) S[mt][t][r] = 0.0f;

            // ---- S = Q·Kh + Q·Kl ----
#pragma unroll
            for (int k16 = 0; k16 < 4; k16++) {
#pragma unroll
                for (int np = 0; np < 4; np++) {
                    uint32_t ko = aoff(16 * np + lr + (lg >> 1) * 8, 2 * k16 + (lg & 1));
                    uint32_t kh0, kh1, kh2, kh3, kl0, kl1, kl2, kl3;
                    ldsm_x4(kh0, kh1, kh2, kh3, stb + ko);
                    ldsm_x4(kl0, kl1, kl2, kl3, stb + AT_B + ko);
#pragma unroll
                    for (int mt = 0; mt < 2; mt++) {
                        mma_f16(S[mt][2 * np + 0], qf[mt][k16], kh0, kh1);
                        mma_f16(S[mt][2 * np + 1], qf[mt][k16], kh2, kh3);
                        mma_f16(S[mt][2 * np + 0], qf[mt][k16], kl0, kl1);
                        mma_f16(S[mt][2 * np + 1], qf[mt][k16], kl2, kl3);
                    }
                }
            }

            // ---- causal mask ----
            if (kb + 63 > wrow0) {
#pragma unroll
                for (int mt = 0; mt < 2; mt++) {
                    int mr = myrow0 + mt * 16;
#pragma unroll
                    for (int j = 0; j < 8; j++) {
#pragma unroll
                        for (int cc = 0; cc < 2; cc++) {
                            int key = kb + 8 * j + 2 * t4 + cc;
                            if (key > mr)     S[mt][j][cc]     = -INFINITY;
                            if (key > mr + 8) S[mt][j][2 + cc] = -INFINITY;
                        }
                    }
                }
            }

            // ---- online softmax (base 2) ----
            float alpha[2][2];
#pragma unroll
            for (int mt = 0; mt < 2; mt++) {
#pragma unroll
                for (int r = 0; r < 2; r++) {
                    float mx = S[mt][0][2 * r];
#pragma unroll
                    for (int j = 0; j < 8; j++) {
                        mx = fmaxf(mx, S[mt][j][2 * r]);
                        mx = fmaxf(mx, S[mt][j][2 * r + 1]);
                    }
                    mx = fmaxf(mx, __shfl_xor_sync(0xffffffffu, mx, 1));
                    mx = fmaxf(mx, __shfl_xor_sync(0xffffffffu, mx, 2));
                    float mn = fmaxf(mrow[mt][r], mx);
                    alpha[mt][r] = fexp2(mrow[mt][r] - mn);
                    float rs = 0.0f;
#pragma unroll
                    for (int j = 0; j < 8; j++) {
                        float p0 = fexp2(S[mt][j][2 * r] - mn);
                        float p1 = fexp2(S[mt][j][2 * r + 1] - mn);
                        S[mt][j][2 * r] = p0;
                        S[mt][j][2 * r + 1] = p1;
                        rs += p0 + p1;
                    }
                    rs += __shfl_xor_sync(0xffffffffu, rs, 1);
                    rs += __shfl_xor_sync(0xffffffffu, rs, 2);
                    lrow[mt][r] = lrow[mt][r] * alpha[mt][r] + rs;
                    mrow[mt][r] = mn;
                }
            }
            bool noresc = (alpha[0][0] == 1.0f) && (alpha[0][1] == 1.0f) &&
                          (alpha[1][0] == 1.0f) && (alpha[1][1] == 1.0f);
            if (!__all_sync(0xffffffffu, noresc)) {
#pragma unroll
                for (int mt = 0; mt < 2; mt++)
#pragma unroll
                    for (int t = 0; t < 8; t++)
#pragma unroll
                        for (int r = 0; r < 2; r++) {
                            ctx[mt][t][2 * r] *= alpha[mt][r];
                            ctx[mt][t][2 * r + 1] *= alpha[mt][r];
                        }
            }

            // ---- pack P (frees S) ----
            uint32_t pf[2][4][4];
#pragma unroll
            for (int mt = 0; mt < 2; mt++)
#pragma unroll
                for (int j2 = 0; j2 < 4; j2++) {
                    pf[mt][j2][0] = h2pack(S[mt][2 * j2][0],     S[mt][2 * j2][1]);
                    pf[mt][j2][1] = h2pack(S[mt][2 * j2][2],     S[mt][2 * j2][3]);
                    pf[mt][j2][2] = h2pack(S[mt][2 * j2 + 1][0], S[mt][2 * j2 + 1][1]);
                    pf[mt][j2][3] = h2pack(S[mt][2 * j2 + 1][2], S[mt][2 * j2 + 1][3]);
                }

            // ---- ctx += P·Vh + P·Vl ----
#pragma unroll
            for (int j2 = 0; j2 < 4; j2++) {
#pragma unroll
                for (int np = 0; np < 4; np++) {
                    uint32_t vo = aoff(16 * np + lr + (lg >> 1) * 8, 2 * j2 + (lg & 1));
                    uint32_t vh0, vh1, vh2, vh3, vl0, vl1, vl2, vl3;
                    ldsm_x4(vh0, vh1, vh2, vh3, stb + 2 * AT_B + vo);
                    ldsm_x4(vl0, vl1, vl2, vl3, stb + 3 * AT_B + vo);
#pragma unroll
                    for (int mt = 0; mt < 2; mt++) {
                        mma_f16(ctx[mt][2 * np + 0], pf[mt][j2], vh0, vh1);
                        mma_f16(ctx[mt][2 * np + 1], pf[mt][j2], vh2, vh3);
                        mma_f16(ctx[mt][2 * np + 0], pf[mt][j2], vl0, vl1);
                        mma_f16(ctx[mt][2 * np + 1], pf[mt][j2], vl2, vl3);
                    }
                }
            }
        }

        slot = slot + 1; if (slot >= ANSTG) slot = 0;
    }

    // ---- epilogue ----
#pragma unroll
    for (int mt = 0; mt < 2; mt++) {
#pragma unroll
        for (int r = 0; r < 2; r++) {
            float inv = 1.0f / lrow[mt][r];
            int srow = wrow0 + mt * 16 + g + 8 * r;
            size_t base = ((size_t)b * SS + srow) * DD + h * DHD;
#pragma unroll
            for (int t = 0; t < 8; t++) {
                size_t idx = base + 8 * t + 2 * t4;
                *reinterpret_cast<uint32_t*>(&g_ch[idx]) =
                    h2pack(ctx[mt][t][2 * r] * inv, ctx[mt][t][2 * r + 1] * inv);
            }
        }
    }
}

// ---------------------------------------------------------------------------
extern "C" void kernel_launch(void* const* d_in, const int* in_sizes, int n_in,
                              void* d_out, int out_size) {
    const float* x  = (const float*)d_in[0];
    const float* Wq = (const float*)d_in[1];
    const float* bq = (const float*)d_in[2];
    const float* Wk = (const float*)d_in[3];
    const float* bk = (const float*)d_in[4];
    const float* Wv = (const float*)d_in[5];
    const float* bv = (const float*)d_in[6];
    const float* Wo = (const float*)d_in[7];
    const float* bo = (const float*)d_in[8];
    float* out = (float*)d_out;

    __half *pxh, *pch;
    cudaGetSymbolAddress((void**)&pxh, g_xh);
    cudaGetSymbolAddress((void**)&pch, g_ch);

    cudaFuncSetAttribute(gemm_tc_kernel<0>, cudaFuncAttributeMaxDynamicSharedMemorySize, GEMM_SMEM);
    cudaFuncSetAttribute(gemm_tc_kernel<1>, cudaFuncAttributeMaxDynamicSharedMemorySize, GEMM_SMEM);
    cudaFuncSetAttribute(attn_kernel, cudaFuncAttributeMaxDynamicSharedMemorySize, ATT_SMEM);

    convert_x_kernel<<<(MROWS * DD / 4) / 256, 256>>>(x, pxh);

    dim3 tgrid(DD / 32, DD / 32, 4);
    convert_wT_kernel<<<tgrid, 256>>>(Wq, Wk, Wv, Wo);

    dim3 ggrid(DD / BN, MROWS / BM, 3);
    gemm_tc_kernel<1><<<ggrid, 256, GEMM_SMEM>>>(pxh, bq, bk, bv, nullptr);

    dim3 agrid(SS / 128, HN, BB);
    attn_kernel<<<agrid, ATHR, ATT_SMEM>>>();

    dim3 ogrid(DD / BN, MROWS / BM, 1);
    gemm_tc_kernel<0><<<ogrid, 256, GEMM_SMEM>>>(pch, bo, nullptr, nullptr, out);
}

// round 16
// speedup vs baseline: 1.0017x; 1.0017x over previous
#include <cuda_runtime.h>
#include <cuda_fp16.h>
#include <math.h>
#include <stdint.h>

#define HN 16
#define DHD 64
#define DD 1024
#define BB 2
#define SS 2048
#define MROWS (BB * SS)   // 4096

// ------------------------- device scratch (no allocs) -----------------------
__device__ __align__(16) __half g_xh[MROWS * DD];            // X fp16 (single)
__device__ __align__(16) __half g_wht[4][DD * DD];           // W^T hi [N][K]
__device__ __align__(16) __half g_wlt[4][DD * DD];           // W^T lo [N][K]
__device__ __align__(16) __half g_qh[BB * HN * SS * DHD];    // Q fp16, scaled 0.125*log2e
__device__ __align__(16) __half g_kh[BB * HN * SS * DHD];    // K hi
__device__ __align__(16) __half g_kl[BB * HN * SS * DHD];    // K lo
__device__ __align__(16) __half g_vth[BB * HN * SS * DHD];   // V^T hi [b,h,dh,s]
__device__ __align__(16) __half g_vtl[BB * HN * SS * DHD];   // V^T lo
__device__ __align__(16) __half g_ch[MROWS * DD];            // ctx fp16 (single)

#define QSCALE (0.125f * 1.44269504088896340736f)

// ------------------------------ ptx helpers --------------------------------
__device__ __forceinline__ uint32_t smem_u32(const void* p) {
    return (uint32_t)__cvta_generic_to_shared(p);
}
__device__ __forceinline__ void cpa16(uint32_t d, const void* s) {
    asm volatile("cp.async.cg.shared.global [%0], [%1], 16;" :: "r"(d), "l"(s));
}
__device__ __forceinline__ void cpa_commit() {
    asm volatile("cp.async.commit_group;" ::: "memory");
}
__device__ __forceinline__ void ldsm_x4(uint32_t& d0, uint32_t& d1, uint32_t& d2,
                                        uint32_t& d3, uint32_t addr) {
    asm volatile("ldmatrix.sync.aligned.m8n8.x4.shared.b16 {%0,%1,%2,%3}, [%4];"
                 : "=r"(d0), "=r"(d1), "=r"(d2), "=r"(d3) : "r"(addr));
}
__device__ __forceinline__ void mma_f16(float* c, const uint32_t* a,
                                        uint32_t b0, uint32_t b1) {
    asm volatile(
        "mma.sync.aligned.m16n8k16.row.col.f32.f16.f16.f32 "
        "{%0,%1,%2,%3}, {%4,%5,%6,%7}, {%8,%9}, {%0,%1,%2,%3};"
        : "+f"(c[0]), "+f"(c[1]), "+f"(c[2]), "+f"(c[3])
        : "r"(a[0]), "r"(a[1]), "r"(a[2]), "r"(a[3]), "r"(b0), "r"(b1));
}
__device__ __forceinline__ uint32_t h2pack(float x, float y) {
    __half2 t = __floats2half2_rn(x, y);
    return *reinterpret_cast<uint32_t*>(&t);
}
__device__ __forceinline__ void split2h(float x, float y, uint32_t& h, uint32_t& l) {
    __half2 hh = __floats2half2_rn(x, y);
    __half2 ll = __floats2half2_rn(x - __low2float(hh), y - __high2float(hh));
    h = *reinterpret_cast<uint32_t*>(&hh);
    l = *reinterpret_cast<uint32_t*>(&ll);
}
__device__ __forceinline__ float fexp2(float x) {
    float y;
    asm("ex2.approx.ftz.f32 %0, %1;" : "=f"(y) : "f"(x));
    return y;
}

// ---------------------------- conversion kernels ---------------------------
__global__ __launch_bounds__(256)
void convert_x_kernel(const float* __restrict__ X, __half* __restrict__ Xh) {
    size_t i = (size_t)blockIdx.x * blockDim.x + threadIdx.x;
    float4 v = reinterpret_cast<const float4*>(X)[i];
    uint2 o;
    o.x = h2pack(v.x, v.y);
    o.y = h2pack(v.z, v.w);
    reinterpret_cast<uint2*>(Xh)[i] = o;
}

__global__ __launch_bounds__(256)
void convert_wT_kernel(const float* __restrict__ W0, const float* __restrict__ W1,
                       const float* __restrict__ W2, const float* __restrict__ W3) {
    __shared__ float t[32][33];
    const int w = blockIdx.z;
    const float* W = (w == 0) ? W0 : (w == 1) ? W1 : (w == 2) ? W2 : W3;
    __half* WhT = g_wht[w];
    __half* WlT = g_wlt[w];
    int n0 = blockIdx.x * 32, k0 = blockIdx.y * 32;
    int tx = threadIdx.x & 31;
    int ty = threadIdx.x >> 5;
#pragma unroll
    for (int j = 0; j < 4; j++)
        t[ty + 8 * j][tx] = W[(size_t)(k0 + ty + 8 * j) * DD + n0 + tx];
    __syncthreads();
#pragma unroll
    for (int j = 0; j < 4; j++) {
        float v = t[tx][ty + 8 * j];
        __half h = __float2half_rn(v);
        size_t o = (size_t)(n0 + ty + 8 * j) * DD + k0 + tx;
        WhT[o] = h;
        WlT[o] = __float2half_rn(v - __half2float(h));
    }
}

// ------------------------- mma.sync fp16 2-pass GEMM ------------------------
#define BM 128
#define BN 128
#define BK 32
#define NCH (DD / BK)       // 32
#define MAT_B (BM * BK * 2) // 8192
#define STG_B (3 * MAT_B)   // 24576 : A, Bh, Bl
#define NSTG 4
#define GEMM_SMEM (NSTG * STG_B)  // 98304

__device__ __forceinline__ uint32_t soff(int r, int c) {
    return (uint32_t)(r * 64 + ((c ^ ((r >> 1) & 3)) << 4));
}

__device__ __forceinline__ void load_stage(uint32_t sb,
                                           const __half* A,
                                           const __half* Bh, const __half* Bl,
                                           int m0, int n0, int chunk, int tid) {
    const int kb = chunk * BK;
#pragma unroll
    for (int t = 0; t < 6; t++) {
        int idx = t * 256 + tid;        // 0..1535
        int mat = idx >> 9;             // 0..2
        int i = idx & 511;
        int r = i >> 2;
        int c = i & 3;
        uint32_t d = sb + mat * MAT_B + soff(r, c);
        const __half* src;
        if (mat == 0)      src = A  + (size_t)(m0 + r) * DD + kb + c * 8;
        else if (mat == 1) src = Bh + (size_t)(n0 + r) * DD + kb + c * 8;
        else               src = Bl + (size_t)(n0 + r) * DD + kb + c * 8;
        cpa16(d, (const void*)src);
    }
    cpa_commit();
}

// QKV=1: grid.z = proj (0=Q scaled single, 1=K split, 2=V split transposed)
// QKV=0: fp32 row-major out + bias0.
template <int QKV>
__global__ __launch_bounds__(256, 2)
void gemm_tc_kernel(const __half* __restrict__ A,
                    const float* __restrict__ b0, const float* __restrict__ b1,
                    const float* __restrict__ b2, float* __restrict__ Y) {
    extern __shared__ char dsm[];
    const int tid = threadIdx.x;
    const int lane = tid & 31;
    const int wid = tid >> 5;
    const int mwarp = wid & 3;
    const int nwarp = wid >> 2;
    const int n0 = blockIdx.x * BN;
    const int m0 = blockIdx.y * BM;
    const int proj = QKV ? blockIdx.z : 3;

    const __half* Bh = g_wht[proj];
    const __half* Bl = g_wlt[proj];
    const float* bias = QKV ? ((proj == 0) ? b0 : (proj == 1) ? b1 : b2) : b0;

    const uint32_t sbase = smem_u32(dsm);
    const int lr = lane & 7;
    const int lg = lane >> 3;

    float acc[2][8][4];
#pragma unroll
    for (int mt = 0; mt < 2; mt++)
#pragma unroll
        for (int nt = 0; nt < 8; nt++)
#pragma unroll
            for (int r = 0; r < 4; r++) acc[mt][nt][r] = 0.0f;

    load_stage(sbase, A, Bh, Bl, m0, n0, 0, tid);
    load_stage(sbase + STG_B, A, Bh, Bl, m0, n0, 1, tid);
    load_stage(sbase + 2 * STG_B, A, Bh, Bl, m0, n0, 2, tid);

    for (int c = 0; c < NCH; c++) {
        const int rem = NCH - 1 - c;
        if (rem >= 2)      asm volatile("cp.async.wait_group 2;" ::: "memory");
        else if (rem == 1) asm volatile("cp.async.wait_group 1;" ::: "memory");
        else               asm volatile("cp.async.wait_group 0;" ::: "memory");
        __syncthreads();
        if (c + 3 < NCH)
            load_stage(sbase + (uint32_t)((c + 3) & 3) * STG_B, A, Bh, Bl, m0, n0, c + 3, tid);

        const uint32_t sb = sbase + (uint32_t)(c & 3) * STG_B;
        const uint32_t sA  = sb;
        const uint32_t sBh = sb + MAT_B;
        const uint32_t sBl = sb + 2 * MAT_B;

#pragma unroll
        for (int ks = 0; ks < 2; ks++) {
            const int c0 = ks * 2;
            uint32_t av[2][4];
#pragma unroll
            for (int mt = 0; mt < 2; mt++) {
                int row = mwarp * 32 + mt * 16 + lr + (lg & 1) * 8;
                int ch = c0 + (lg >> 1);
                ldsm_x4(av[mt][0], av[mt][1], av[mt][2], av[mt][3], sA + soff(row, ch));
            }
#pragma unroll
            for (int np = 0; np < 4; np++) {
                int brow = nwarp * 64 + np * 16 + lr + (lg >> 1) * 8;
                int bch = c0 + (lg & 1);
                uint32_t boff = soff(brow, bch);
                uint32_t bh0, bh1, bh2, bh3, bl0, bl1, bl2, bl3;
                ldsm_x4(bh0, bh1, bh2, bh3, sBh + boff);
                ldsm_x4(bl0, bl1, bl2, bl3, sBl + boff);
#pragma unroll
                for (int mt = 0; mt < 2; mt++) {
                    mma_f16(acc[mt][2 * np + 0], av[mt], bh0, bh1);
                    mma_f16(acc[mt][2 * np + 1], av[mt], bh2, bh3);
                    mma_f16(acc[mt][2 * np + 0], av[mt], bl0, bl1);
                    mma_f16(acc[mt][2 * np + 1], av[mt], bl2, bl3);
                }
            }
        }
    }

    // epilogue
#pragma unroll
    for (int mt = 0; mt < 2; mt++) {
#pragma unroll
        for (int half = 0; half < 2; half++) {
            int gm = m0 + mwarp * 32 + mt * 16 + (lane >> 2) + half * 8;
            int bidx = gm >> 11;
            int sidx = gm & (SS - 1);
#pragma unroll
            for (int nt = 0; nt < 8; nt++) {
                int ncol = n0 + nwarp * 64 + nt * 8 + 2 * (lane & 3);
                float2 bv = *reinterpret_cast<const float2*>(&bias[ncol]);
                float ox = acc[mt][nt][2 * half + 0] + bv.x;
                float oy = acc[mt][nt][2 * half + 1] + bv.y;
                if (!QKV) {
                    float2 o = {ox, oy};
                    *reinterpret_cast<float2*>(&Y[(size_t)gm * DD + ncol]) = o;
                } else {
                    int hh = ncol >> 6;
                    int dh = ncol & (DHD - 1);
                    if (proj == 0) {
                        size_t base = (((size_t)bidx * HN + hh) * SS + sidx) * DHD + dh;
                        *reinterpret_cast<uint32_t*>(&g_qh[base]) =
                            h2pack(ox * QSCALE, oy * QSCALE);
                    } else if (proj == 1) {
                        uint32_t hq, lq;
                        split2h(ox, oy, hq, lq);
                        size_t base = (((size_t)bidx * HN + hh) * SS + sidx) * DHD + dh;
                        *reinterpret_cast<uint32_t*>(&g_kh[base]) = hq;
                        *reinterpret_cast<uint32_t*>(&g_kl[base]) = lq;
                    } else {
                        uint32_t hq, lq;
                        split2h(ox, oy, hq, lq);
                        size_t base = (((size_t)bidx * HN + hh) * DHD + dh) * SS + sidx;
                        __half2 hv = *reinterpret_cast<__half2*>(&hq);
                        __half2 lv = *reinterpret_cast<__half2*>(&lq);
                        g_vth[base] = __low2half(hv); g_vth[base + SS] = __high2half(hv);
                        g_vtl[base] = __low2half(lv); g_vtl[base + SS] = __high2half(lv);
                    }
                }
            }
        }
    }
}

// ---------------------- tensor-core flash attention (fp16) ------------------
// 4 warps x 32 q-rows each (2 m16 tiles): K/V ldsm amortized over 2x MMA.
// 3-stage KV ring, one barrier/tile, base-2 softmax, per-warp tile skip.
#define AQ_B 16384                 // Q: 128 rows x 128B
#define AT_B 8192                  // K/V^T: 64 rows x 128B
#define ASTG_B (4 * AT_B)          // Kh, Kl, VTh, VTl = 32768
#define ANSTG 3
#define ATT_SMEM (AQ_B + ANSTG * ASTG_B)  // 114688
#define ATHR 128

__device__ __forceinline__ uint32_t aoff(int r, int c) {
    return (uint32_t)(r * 128 + ((c ^ (r & 7)) << 4));
}

__device__ __forceinline__ void att_load_kv(uint32_t sb, size_t hb, int s0, int tid) {
#pragma unroll
    for (int t = 0; t < 16; t++) {
        int slot = t * ATHR + tid;      // 0..2047
        int mat = slot >> 9;
        int i = slot & 511;
        int r = i >> 3;
        int c = i & 7;
        uint32_t d = sb + mat * AT_B + aoff(r, c);
        const __half* src;
        if (mat == 0)      src = g_kh + hb + (size_t)(s0 + r) * DHD + c * 8;
        else if (mat == 1) src = g_kl + hb + (size_t)(s0 + r) * DHD + c * 8;
        else if (mat == 2) src = g_vth + hb + (size_t)r * SS + s0 + c * 8;
        else               src = g_vtl + hb + (size_t)r * SS + s0 + c * 8;
        cpa16(d, (const void*)src);
    }
}

__global__ __launch_bounds__(ATHR, 2)
void attn_kernel() {
    extern __shared__ char asm_[];
    const uint32_t sbase = smem_u32(asm_);
    const uint32_t kvbase = sbase + AQ_B;
    const int tid = threadIdx.x;
    const int lane = tid & 31;
    const int wid = tid >> 5;        // 0..3
    const int lr = lane & 7;
    const int lg = lane >> 3;
    const int g = lane >> 2;
    const int t4 = lane & 3;

    const int Qi = 15 - blockIdx.x;
    const int h = blockIdx.y;
    const int b = blockIdx.z;
    const int q0 = Qi * 128;
    const size_t hb = ((size_t)b * HN + h) * SS * DHD;
    const int ntiles = 2 * Qi + 2;

    {   // prologue: Q + stage0 (group 0); stage1 (group 1)
#pragma unroll
        for (int t = 0; t < 8; t++) {
            int idx = t * ATHR + tid;    // 0..1023
            int r = idx >> 3;
            int c = idx & 7;
            cpa16(sbase + aoff(r, c), (const void*)(g_qh + hb + (size_t)(q0 + r) * DHD + c * 8));
        }
        att_load_kv(kvbase, hb, 0, tid);
        cpa_commit();
        att_load_kv(kvbase + ASTG_B, hb, 64, tid);
        cpa_commit();
    }

    float S[2][8][4];
    float ctx[2][8][4];
    uint32_t qf[2][4][4];
    float mrow[2][2] = {{-INFINITY, -INFINITY}, {-INFINITY, -INFINITY}};
    float lrow[2][2] = {{0.0f, 0.0f}, {0.0f, 0.0f}};
#pragma unroll
    for (int mt = 0; mt < 2; mt++)
#pragma unroll
        for (int t = 0; t < 8; t++)
#pragma unroll
            for (int r = 0; r < 4; r++) ctx[mt][t][r] = 0.0f;

    const int wrow0 = q0 + wid * 32;             // warp's first row
    const int myrow0 = wrow0 + g;                // mt=0 base row for this thread
    int slot = 0;

    for (int kt = 0; kt < ntiles; kt++) {
        const uint32_t stb = kvbase + (uint32_t)slot * ASTG_B;
        const int rem = ntiles - 1 - kt;
        if (rem >= 1) asm volatile("cp.async.wait_group 1;" ::: "memory");
        else          asm volatile("cp.async.wait_group 0;" ::: "memory");
        __syncthreads();

        if (kt == 0) {
#pragma unroll
            for (int mt = 0; mt < 2; mt++)
#pragma unroll
                for (int k16 = 0; k16 < 4; k16++) {
                    uint32_t qo = aoff(wid * 32 + mt * 16 + lr + (lg & 1) * 8,
                                       2 * k16 + (lg >> 1));
                    ldsm_x4(qf[mt][k16][0], qf[mt][k16][1], qf[mt][k16][2],
                            qf[mt][k16][3], sbase + qo);
                }
        }
        // prefetch tile kt+2 BEFORE compute
        if (kt + 2 < ntiles) {
            int ns = slot + 2; if (ns >= ANSTG) ns -= ANSTG;
            att_load_kv(kvbase + (uint32_t)ns * ASTG_B, hb, (kt + 2) * 64, tid);
            cpa_commit();
        }

        const int kb = kt * 64;
        if (kb <= wrow0 + 31) {   // warp has at least one unmasked row
#pragma unroll
            for (int mt = 0; mt < 2; mt++)
#pragma unroll
                for (int t = 0; t < 8; t++)
#pragma unroll
                    for (int r = 0; r < 4; r++) S[mt][t][r] = 0.0f;

            // ---- S = Q·Kh + Q·Kl ----
#pragma unroll
            for (int k16 = 0; k16 < 4; k16++) {
#pragma unroll
                for (int np = 0; np < 4; np++) {
                    uint32_t ko = aoff(16 * np + lr + (lg >> 1) * 8, 2 * k16 + (lg & 1));
                    uint32_t kh0, kh1, kh2, kh3, kl0, kl1, kl2, kl3;
                    ldsm_x4(kh0, kh1, kh2, kh3, stb + ko);
                    ldsm_x4(kl0, kl1, kl2, kl3, stb + AT_B + ko);
#pragma unroll
                    for (int mt = 0; mt < 2; mt++) {
                        mma_f16(S[mt][2 * np + 0], qf[mt][k16], kh0, kh1);
                        mma_f16(S[mt][2 * np + 1], qf[mt][k16], kh2, kh3);
                        mma_f16(S[mt][2 * np + 0], qf[mt][k16], kl0, kl1);
                        mma_f16(S[mt][2 * np + 1], qf[mt][k16], kl2, kl3);
                    }
                }
            }

            // ---- causal mask ----
            if (kb + 63 > wrow0) {
#pragma unroll
                for (int mt = 0; mt < 2; mt++) {
                    int mr = myrow0 + mt * 16;
#pragma unroll
                    for (int j = 0; j < 8; j++) {
#pragma unroll
                        for (int cc = 0; cc < 2; cc++) {
                            int key = kb + 8 * j + 2 * t4 + cc;
                            if (key > mr)     S[mt][j][cc]     = -INFINITY;
                            if (key > mr + 8) S[mt][j][2 + cc] = -INFINITY;
                        }
                    }
                }
            }

            // ---- online softmax (base 2) ----
            float alpha[2][2];
#pragma unroll
            for (int mt = 0; mt < 2; mt++) {
#pragma unroll
                for (int r = 0; r < 2; r++) {
                    float mx = S[mt][0][2 * r];
#pragma unroll
                    for (int j = 0; j < 8; j++) {
                        mx = fmaxf(mx, S[mt][j][2 * r]);
                        mx = fmaxf(mx, S[mt][j][2 * r + 1]);
                    }
                    mx = fmaxf(mx, __shfl_xor_sync(0xffffffffu, mx, 1));
                    mx = fmaxf(mx, __shfl_xor_sync(0xffffffffu, mx, 2));
                    float mn = fmaxf(mrow[mt][r], mx);
                    alpha[mt][r] = fexp2(mrow[mt][r] - mn);
                    float rs = 0.0f;
#pragma unroll
                    for (int j = 0; j < 8; j++) {
                        float p0 = fexp2(S[mt][j][2 * r] - mn);
                        float p1 = fexp2(S[mt][j][2 * r + 1] - mn);
                        S[mt][j][2 * r] = p0;
                        S[mt][j][2 * r + 1] = p1;
                        rs += p0 + p1;
                    }
                    rs += __shfl_xor_sync(0xffffffffu, rs, 1);
                    rs += __shfl_xor_sync(0xffffffffu, rs, 2);
                    lrow[mt][r] = lrow[mt][r] * alpha[mt][r] + rs;
                    mrow[mt][r] = mn;
                }
            }
            bool noresc = (alpha[0][0] == 1.0f) && (alpha[0][1] == 1.0f) &&
                          (alpha[1][0] == 1.0f) && (alpha[1][1] == 1.0f);
            if (!__all_sync(0xffffffffu, noresc)) {
#pragma unroll
                for (int mt = 0; mt < 2; mt++)
#pragma unroll
                    for (int t = 0; t < 8; t++)
#pragma unroll
                        for (int r = 0; r < 2; r++) {
                            ctx[mt][t][2 * r] *= alpha[mt][r];
                            ctx[mt][t][2 * r + 1] *= alpha[mt][r];
                        }
            }

            // ---- pack P (frees S) ----
            uint32_t pf[2][4][4];
#pragma unroll
            for (int mt = 0; mt < 2; mt++)
#pragma unroll
                for (int j2 = 0; j2 < 4; j2++) {
                    pf[mt][j2][0] = h2pack(S[mt][2 * j2][0],     S[mt][2 * j2][1]);
                    pf[mt][j2][1] = h2pack(S[mt][2 * j2][2],     S[mt][2 * j2][3]);
                    pf[mt][j2][2] = h2pack(S[mt][2 * j2 + 1][0], S[mt][2 * j2 + 1][1]);
                    pf[mt][j2][3] = h2pack(S[mt][2 * j2 + 1][2], S[mt][2 * j2 + 1][3]);
                }

            // ---- ctx += P·Vh + P·Vl ----
#pragma unroll
            for (int j2 = 0; j2 < 4; j2++) {
#pragma unroll
                for (int np = 0; np < 4; np++) {
                    uint32_t vo = aoff(16 * np + lr + (lg >> 1) * 8, 2 * j2 + (lg & 1));
                    uint32_t vh0, vh1, vh2, vh3, vl0, vl1, vl2, vl3;
                    ldsm_x4(vh0, vh1, vh2, vh3, stb + 2 * AT_B + vo);
                    ldsm_x4(vl0, vl1, vl2, vl3, stb + 3 * AT_B + vo);
#pragma unroll
                    for (int mt = 0; mt < 2; mt++) {
                        mma_f16(ctx[mt][2 * np + 0], pf[mt][j2], vh0, vh1);
                        mma_f16(ctx[mt][2 * np + 1], pf[mt][j2], vh2, vh3);
                        mma_f16(ctx[mt][2 * np + 0], pf[mt][j2], vl0, vl1);
                        mma_f16(ctx[mt][2 * np + 1], pf[mt][j2], vl2, vl3);
                    }
                }
            }
        }

        slot = slot + 1; if (slot >= ANSTG) slot = 0;
    }

    // ---- epilogue ----
#pragma unroll
    for (int mt = 0; mt < 2; mt++) {
#pragma unroll
        for (int r = 0; r < 2; r++) {
            float inv = 1.0f / lrow[mt][r];
            int srow = wrow0 + mt * 16 + g + 8 * r;
            size_t base = ((size_t)b * SS + srow) * DD + h * DHD;
#pragma unroll
            for (int t = 0; t < 8; t++) {
                size_t idx = base + 8 * t + 2 * t4;
                *reinterpret_cast<uint32_t*>(&g_ch[idx]) =
                    h2pack(ctx[mt][t][2 * r] * inv, ctx[mt][t][2 * r + 1] * inv);
            }
        }
    }
}

// ---------------------------------------------------------------------------
extern "C" void kernel_launch(void* const* d_in, const int* in_sizes, int n_in,
                              void* d_out, int out_size) {
    const float* x  = (const float*)d_in[0];
    const float* Wq = (const float*)d_in[1];
    const float* bq = (const float*)d_in[2];
    const float* Wk = (const float*)d_in[3];
    const float* bk = (const float*)d_in[4];
    const float* Wv = (const float*)d_in[5];
    const float* bv = (const float*)d_in[6];
    const float* Wo = (const float*)d_in[7];
    const float* bo = (const float*)d_in[8];
    float* out = (float*)d_out;

    __half *pxh, *pch;
    cudaGetSymbolAddress((void**)&pxh, g_xh);
    cudaGetSymbolAddress((void**)&pch, g_ch);

    cudaFuncSetAttribute(gemm_tc_kernel<0>, cudaFuncAttributeMaxDynamicSharedMemorySize, GEMM_SMEM);
    cudaFuncSetAttribute(gemm_tc_kernel<1>, cudaFuncAttributeMaxDynamicSharedMemorySize, GEMM_SMEM);
    cudaFuncSetAttribute(attn_kernel, cudaFuncAttributeMaxDynamicSharedMemorySize, ATT_SMEM);

    convert_x_kernel<<<(MROWS * DD / 4) / 256, 256>>>(x, pxh);

    dim3 tgrid(DD / 32, DD / 32, 4);
    convert_wT_kernel<<<tgrid, 256>>>(Wq, Wk, Wv, Wo);

    dim3 ggrid(DD / BN, MROWS / BM, 3);
    gemm_tc_kernel<1><<<ggrid, 256, GEMM_SMEM>>>(pxh, bq, bk, bv, nullptr);

    dim3 agrid(SS / 128, HN, BB);
    attn_kernel<<<agrid, ATHR, ATT_SMEM>>>();

    dim3 ogrid(DD / BN, MROWS / BM, 1);
    gemm_tc_kernel<0><<<ogrid, 256, GEMM_SMEM>>>(pch, bo, nullptr, nullptr, out);
}